// round 2
// baseline (speedup 1.0000x reference)
#include <cuda_runtime.h>

// TT-embedding, refactored:
//   core0: (1,8,40,16)    A[x][p][b]     idx = x*640 + p*16 + b
//   core1: (16,8,32,16)   M[b][y][q][c]  idx = b*4096 + y*512 + q*16 + c
//   core2: (16,16,25,1)   C[c][z][r]     idx = c*400 + z*25 + r
//   id -> p = id/800, q = (id%800)/25, r = id%25
//   out[tok][x*128+y*16+z] = sum_{b,c} A[x][p][b] M[b][y][q][c] C[c][z][r]
//
// Stage 1: s[p*32+q][c][x*8+y] = sum_b A[x][p][b] * M[b][y][q][c]
//          (1280 x 1024 table, 5.2 MB -> lives in L2)
//          plus transposed core2: c2t[r][c][z] (6400 floats)
// Stage 2: out[tok][xy][z] = sum_c s[pq][c][xy] * c2t[r][c][z]
//          one warp per token, lane owns xy rows {2l, 2l+1}, packed f32x2 FMA.

#define NTOK   16384
#define GRID_G 296   // 2 blocks per SM on 148 SMs

__device__ float g_s[1280 * 1024];
__device__ float g_c2t[6400];
__device__ int   g_ids64;

// ---------------------------------------------------------------------------
// Stage 1: build s table (+ c2t transpose + id-width sniff in block 0)
// ---------------------------------------------------------------------------
__global__ __launch_bounds__(256) void build_s(const float* __restrict__ c0,
                                               const float* __restrict__ c1,
                                               const float* __restrict__ c2,
                                               const int* __restrict__ ids) {
    int pq = blockIdx.x;
    int p = pq >> 5, q = pq & 31;

    __shared__ float sA[128];    // [x][b]
    __shared__ float sM[2048];   // [b][y][c]

    int t = threadIdx.x;
    if (t < 128) {
        int x = t >> 4, b = t & 15;
        sA[t] = c0[x * 640 + p * 16 + b];
    }
    for (int i = t; i < 2048; i += 256) {
        int b = i >> 7, y = (i >> 4) & 7, cc = i & 15;
        sM[i] = c1[b * 4096 + y * 512 + q * 16 + cc];
    }
    __syncthreads();

    for (int o = t; o < 1024; o += 256) {
        int cc = o >> 6, xy = o & 63;
        int x = xy >> 3, y = xy & 7;
        float acc = 0.f;
#pragma unroll
        for (int b = 0; b < 16; ++b)
            acc += sA[x * 16 + b] * sM[b * 128 + y * 16 + cc];
        g_s[pq * 1024 + o] = acc;
    }

    if (pq == 0) {
        // transpose core2 -> c2t[r][c][z]
        for (int i = t; i < 6400; i += 256) {
            int r = i >> 8, cz = i & 255;
            int cc = cz >> 4, z = cz & 15;
            g_c2t[i] = c2[cc * 400 + z * 25 + r];
        }
        if (t == 0) {
            // ids little-endian int64 => all odd words of first 64 are zero
            int ored = 0;
#pragma unroll
            for (int i = 0; i < 32; ++i) ored |= ids[2 * i + 1];
            g_ids64 = (ored == 0) ? 1 : 0;
        }
    }
}

// ---------------------------------------------------------------------------
// Stage 2: gather. One warp per token (looped); lane l owns xy rows 2l, 2l+1.
// ---------------------------------------------------------------------------
__global__ __launch_bounds__(256) void tt_gather(const int* __restrict__ ids,
                                                 float* __restrict__ out) {
    __shared__ __align__(16) float Cw[6400];   // c2t copy [r][c][z]
    int t = threadIdx.x;
    for (int i = t; i < 6400; i += 256) Cw[i] = g_c2t[i];
    __syncthreads();

    int lane = t & 31, warp = t >> 5;
    int ids64 = g_ids64;

    for (int tok = blockIdx.x * 8 + warp; tok < NTOK; tok += GRID_G * 8) {
        int id = ids64 ? ids[2 * tok] : ids[tok];
        int p = id / 800;
        int rem = id - p * 800;
        int q = rem / 25;
        int r = rem - q * 25;

        const float* srow = g_s + (p * 32 + q) * 1024 + 2 * lane;
        const ulonglong2* crow =
            reinterpret_cast<const ulonglong2*>(Cw + r * 256);

        unsigned long long acc0[8], acc1[8];   // rows 2l, 2l+1; z packed in pairs
#pragma unroll
        for (int j = 0; j < 8; ++j) { acc0[j] = 0ull; acc1[j] = 0ull; }

#pragma unroll 4
        for (int c = 0; c < 16; ++c) {
            float2 sv = *reinterpret_cast<const float2*>(srow + c * 64);
            unsigned long long p0, p1;
            asm("mov.b64 %0,{%1,%1};" : "=l"(p0) : "f"(sv.x));
            asm("mov.b64 %0,{%1,%1};" : "=l"(p1) : "f"(sv.y));
#pragma unroll
            for (int k = 0; k < 4; ++k) {
                ulonglong2 cv = crow[c * 4 + k];   // z = 4k..4k+3 (two f32x2)
                asm("fma.rn.f32x2 %0,%1,%2,%0;" : "+l"(acc0[2 * k])     : "l"(p0), "l"(cv.x));
                asm("fma.rn.f32x2 %0,%1,%2,%0;" : "+l"(acc0[2 * k + 1]) : "l"(p0), "l"(cv.y));
                asm("fma.rn.f32x2 %0,%1,%2,%0;" : "+l"(acc1[2 * k])     : "l"(p1), "l"(cv.x));
                asm("fma.rn.f32x2 %0,%1,%2,%0;" : "+l"(acc1[2 * k + 1]) : "l"(p1), "l"(cv.y));
            }
        }

        // lane writes 32 consecutive floats: rows 2l (16) then 2l+1 (16)
        ulonglong2* o2 = reinterpret_cast<ulonglong2*>(
            out + (size_t)tok * 1024 + lane * 32);
#pragma unroll
        for (int k = 0; k < 4; ++k)
            o2[k] = make_ulonglong2(acc0[2 * k], acc0[2 * k + 1]);
#pragma unroll
        for (int k = 0; k < 4; ++k)
            o2[4 + k] = make_ulonglong2(acc1[2 * k], acc1[2 * k + 1]);
    }
}

// ---------------------------------------------------------------------------
extern "C" void kernel_launch(void* const* d_in, const int* in_sizes, int n_in,
                              void* d_out, int out_size) {
    const float* core0 = (const float*)d_in[0];
    const float* core1 = (const float*)d_in[1];
    const float* core2 = (const float*)d_in[2];
    const int*   ids   = (const int*)d_in[3];
    float* out = (float*)d_out;

    build_s<<<1280, 256>>>(core0, core1, core2, ids);
    tt_gather<<<GRID_G, 256>>>(ids, out);
}